// round 3
// baseline (speedup 1.0000x reference)
#include <cuda_runtime.h>

#define NN   100000
#define EE   1600000
#define KDIN 128
#define DH   64
#define DOUT 32

// ---------------- scratch (static device globals; no allocation) ----------------
__device__ __align__(16) float g_deg [NN];
__device__ __align__(16) float g_dinv[NN];
__device__ __align__(16) float g_h1t [NN * DH];    // x @ W1
__device__ __align__(16) float g_agg1[NN * DH];    // neighbor agg L1, then relu'd h1
__device__ __align__(16) float g_h2t [NN * DOUT];  // h1 @ W2
__device__ __align__(16) float g_agg2[NN * DOUT];  // neighbor agg L2
__device__ __align__(16) float g_coef[EE];         // dinv[src]*dinv[dst]

// ---------------- helpers ----------------
__device__ __forceinline__ void red_add_v4(float4* addr, float a, float b, float c, float d) {
    asm volatile("red.global.add.v4.f32 [%0], {%1,%2,%3,%4};"
                 :: "l"(addr), "f"(a), "f"(b), "f"(c), "f"(d) : "memory");
}

// ---------------- kernels ----------------
__global__ void zero_kernel() {
    int idx = blockIdx.x * blockDim.x + threadIdx.x;
    int stride = gridDim.x * blockDim.x;
    for (int i = idx; i < NN; i += stride)        g_deg[i]  = 0.f;
    for (int i = idx; i < NN * DH; i += stride)   g_agg1[i] = 0.f;
    for (int i = idx; i < NN * DOUT; i += stride) g_agg2[i] = 0.f;
}

__global__ void deg_kernel(const int* __restrict__ dst) {
    int e = blockIdx.x * blockDim.x + threadIdx.x;
    if (e < EE) atomicAdd(&g_deg[dst[e]], 1.0f);
}

__global__ void dinv_kernel() {
    int i = blockIdx.x * blockDim.x + threadIdx.x;
    if (i < NN) g_dinv[i] = rsqrtf(g_deg[i] + 1.0f);
}

// Tiled fp32 GEMM: C[n,BN] = A[n,K] @ W[K,BN]. One block = BM rows, full BN cols.
template<int BM, int BN, int BK, int TM, int TN, int K>
__global__ void gemm_kernel(const float* __restrict__ A, const float* __restrict__ W,
                            float* __restrict__ C, int n) {
    constexpr int TX = BN / TN;
    constexpr int TY = BM / TM;
    constexpr int NT = TX * TY;
    __shared__ float As[BM][BK + 1];
    __shared__ float Ws[BK][BN + 1];
    const int tid = threadIdx.x;
    const int tx = tid % TX, ty = tid / TX;
    const int row0 = blockIdx.x * BM;
    float acc[TM][TN] = {};
    for (int k0 = 0; k0 < K; k0 += BK) {
        for (int i = tid; i < BM * BK; i += NT) {
            int r = i / BK, c = i % BK;
            int gr = row0 + r;
            As[r][c] = (gr < n) ? A[gr * K + k0 + c] : 0.f;
        }
        for (int i = tid; i < BK * BN; i += NT) {
            int r = i / BN, c = i % BN;
            Ws[r][c] = W[(k0 + r) * BN + c];
        }
        __syncthreads();
#pragma unroll
        for (int k = 0; k < BK; k++) {
            float a[TM], b[TN];
#pragma unroll
            for (int i = 0; i < TM; i++) a[i] = As[ty * TM + i][k];
#pragma unroll
            for (int j = 0; j < TN; j++) b[j] = Ws[k][tx * TN + j];
#pragma unroll
            for (int i = 0; i < TM; i++)
#pragma unroll
                for (int j = 0; j < TN; j++)
                    acc[i][j] = fmaf(a[i], b[j], acc[i][j]);
        }
        __syncthreads();
    }
#pragma unroll
    for (int i = 0; i < TM; i++) {
        int gr = row0 + ty * TM + i;
        if (gr < n) {
#pragma unroll
            for (int j = 0; j < TN; j++)
                C[gr * BN + tx * TN + j] = acc[i][j];
        }
    }
}

// Layer-1 edge scatter: 16 float4 chunks per edge (DH=64). Also materializes coef.
__global__ void edge1_kernel(const int* __restrict__ src, const int* __restrict__ dst) {
    int idx = blockIdx.x * blockDim.x + threadIdx.x;   // EE*16 = 25.6M < 2^31
    if (idx >= EE * 16) return;
    int e = idx >> 4;
    int c = idx & 15;
    int s = src[e], d = dst[e];
    float cf = g_dinv[s] * g_dinv[d];
    if (c == 0) g_coef[e] = cf;
    float4 v = reinterpret_cast<const float4*>(g_h1t)[s * 16 + c];
    red_add_v4(reinterpret_cast<float4*>(g_agg1) + d * 16 + c,
               v.x * cf, v.y * cf, v.z * cf, v.w * cf);
}

// Layer-1 epilogue: agg + h*dinv^2 + b1, relu. Result overwrites g_agg1 (input of GEMM2).
__global__ void post1_kernel(const float* __restrict__ b1) {
    int idx = blockIdx.x * blockDim.x + threadIdx.x;
    if (idx >= NN * DH) return;
    int node = idx >> 6;
    int c = idx & 63;
    float di = g_dinv[node];
    float v = g_agg1[idx] + g_h1t[idx] * di * di + b1[c];
    g_agg1[idx] = fmaxf(v, 0.f);
}

// Layer-2 edge scatter: 8 float4 chunks per edge (DOUT=32). Reuses cached coef.
__global__ void edge2_kernel(const int* __restrict__ src, const int* __restrict__ dst) {
    int idx = blockIdx.x * blockDim.x + threadIdx.x;   // EE*8 = 12.8M
    if (idx >= EE * 8) return;
    int e = idx >> 3;
    int c = idx & 7;
    int s = src[e], d = dst[e];
    float cf = g_coef[e];
    float4 v = reinterpret_cast<const float4*>(g_h2t)[s * 8 + c];
    red_add_v4(reinterpret_cast<float4*>(g_agg2) + d * 8 + c,
               v.x * cf, v.y * cf, v.z * cf, v.w * cf);
}

// Layer-2 epilogue + scorer. Warp per node: lane = output channel.
__global__ void final_kernel(const float* __restrict__ b2, const float* __restrict__ fcw,
                             const float* __restrict__ fcb, float* __restrict__ out) {
    int node = blockIdx.x * 8 + (threadIdx.x >> 5);
    int lane = threadIdx.x & 31;
    if (node >= NN) return;
    float di = g_dinv[node];
    int idx = node * 32 + lane;
    float v = g_agg2[idx] + g_h2t[idx] * di * di + b2[lane];
    v = fmaxf(v, 0.f);
    out[NN + idx] = v;                      // h output
    float s = v * fcw[lane];
#pragma unroll
    for (int off = 16; off > 0; off >>= 1)
        s += __shfl_down_sync(0xffffffffu, s, off);
    if (lane == 0) out[node] = s + fcb[0];  // score output
}

// ---------------- launch ----------------
extern "C" void kernel_launch(void* const* d_in, const int* in_sizes, int n_in,
                              void* d_out, int out_size) {
    const float* x   = (const float*)d_in[0];
    const int*   ei  = (const int*)  d_in[1];
    const float* W1  = (const float*)d_in[2];
    const float* b1  = (const float*)d_in[3];
    const float* W2  = (const float*)d_in[4];
    const float* b2  = (const float*)d_in[5];
    const float* fcw = (const float*)d_in[6];
    const float* fcb = (const float*)d_in[7];
    float* out = (float*)d_out;

    const int* src = ei;
    const int* dst = ei + EE;

    float *h1t, *agg1, *h2t, *agg2;
    cudaGetSymbolAddress((void**)&h1t,  g_h1t);
    cudaGetSymbolAddress((void**)&agg1, g_agg1);
    cudaGetSymbolAddress((void**)&h2t,  g_h2t);
    cudaGetSymbolAddress((void**)&agg2, g_agg2);

    zero_kernel<<<2048, 256>>>();
    deg_kernel<<<(EE + 511) / 512, 512>>>(dst);
    dinv_kernel<<<(NN + 511) / 512, 512>>>();

    // h1t = x @ W1   (K=128, BN=64)
    gemm_kernel<64, 64, 32, 4, 4, KDIN><<<(NN + 63) / 64, 256>>>(x, W1, h1t, NN);
    edge1_kernel<<<(EE * 16 + 255) / 256, 256>>>(src, dst);
    post1_kernel<<<(NN * DH + 255) / 256, 256>>>(b1);

    // h2t = h1 @ W2  (K=64, BN=32)
    gemm_kernel<64, 32, 32, 4, 4, DH><<<(NN + 63) / 64, 128>>>(agg1, W2, h2t, NN);
    edge2_kernel<<<(EE * 8 + 255) / 256, 256>>>(src, dst);

    final_kernel<<<(NN + 7) / 8, 256>>>(b2, fcw, fcb, out);
}

// round 4
// speedup vs baseline: 1.5100x; 1.5100x over previous
#include <cuda_runtime.h>

#define NN   100000
#define EE   1600000
#define KDIN 128
#define DH   64
#define DOUT 32
#define NB_SCAN 98          // ceil(NN/1024)

// ---------------- scratch (static device globals; no allocation) ----------------
__device__ __align__(16) int   g_cnt   [NN];        // in-degree (histogram)
__device__ __align__(16) int   g_rows  [NN];        // CSR row start
__device__ __align__(16) int   g_cursor[NN];        // scatter cursor
__device__ __align__(16) int   g_col   [EE];        // CSR column (src) indices
__device__ __align__(16) int   g_bsum  [128];
__device__ __align__(16) int   g_boff  [128];
__device__ __align__(16) float g_dinv  [NN];
__device__ __align__(16) float g_h1s   [NN * DH];   // (x@W1) * dinv[row]
__device__ __align__(16) float g_x1    [NN * DH];   // relu'd layer-1 output
__device__ __align__(16) float g_h2s   [NN * DOUT]; // (x1@W2) * dinv[row]

// ---------------- CSR build ----------------
__global__ void zero_cnt_kernel() {
    int i = blockIdx.x * blockDim.x + threadIdx.x;
    if (i < NN) g_cnt[i] = 0;
}

__global__ void hist_kernel(const int* __restrict__ dst) {
    int e = blockIdx.x * blockDim.x + threadIdx.x;
    if (e < EE) atomicAdd(&g_cnt[dst[e]], 1);
}

// per-block (1024 elems) exclusive scan; writes in-block exclusive prefix + block sum
__global__ void scan1_kernel() {
    __shared__ int wsum[8], woff[8];
    int tid = threadIdx.x, b = blockIdx.x;
    int lane = tid & 31, warp = tid >> 5;
    int base = b * 1024 + tid * 4;
    int v[4];
#pragma unroll
    for (int j = 0; j < 4; j++) v[j] = (base + j < NN) ? g_cnt[base + j] : 0;
    int ts = v[0] + v[1] + v[2] + v[3];
    int incl = ts;
#pragma unroll
    for (int o = 1; o < 32; o <<= 1) {
        int x = __shfl_up_sync(0xffffffffu, incl, o);
        if (lane >= o) incl += x;
    }
    int excl = incl - ts;
    if (lane == 31) wsum[warp] = incl;
    __syncthreads();
    if (tid == 0) {
        int r = 0;
#pragma unroll
        for (int w = 0; w < 8; w++) { woff[w] = r; r += wsum[w]; }
        g_bsum[b] = r;
    }
    __syncthreads();
    int off = woff[warp] + excl;
    int pre = 0;
#pragma unroll
    for (int j = 0; j < 4; j++) {
        if (base + j < NN) g_rows[base + j] = off + pre;
        pre += v[j];
    }
}

// scan of 98 block sums (single block, Hillis-Steele)
__global__ void scan2_kernel() {
    __shared__ int s[128];
    int t = threadIdx.x;
    int orig = (t < NB_SCAN) ? g_bsum[t] : 0;
    s[t] = orig;
    __syncthreads();
    for (int o = 1; o < 128; o <<= 1) {
        int add = (t >= o) ? s[t - o] : 0;
        __syncthreads();
        s[t] += add;
        __syncthreads();
    }
    if (t < NB_SCAN) g_boff[t] = s[t] - orig;
}

__global__ void scan3_kernel() {
    int i = blockIdx.x * blockDim.x + threadIdx.x;
    if (i >= NN) return;
    int rs = g_rows[i] + g_boff[i >> 10];
    g_rows[i] = rs;
    g_cursor[i] = rs;
    g_dinv[i] = rsqrtf((float)g_cnt[i] + 1.0f);
}

__global__ void scatter_kernel(const int* __restrict__ src, const int* __restrict__ dst) {
    int e = blockIdx.x * blockDim.x + threadIdx.x;
    if (e >= EE) return;
    int d = dst[e];
    int p = atomicAdd(&g_cursor[d], 1);
    g_col[p] = src[e];
}

// ---------------- GEMM: C[r,:] = (A[r,:] @ W) * dinv[r], whole-K in smem ----------------
template<int BM, int BN, int K, int TM, int TN>
__global__ void __launch_bounds__(256, 2)
gemm_dinv(const float* __restrict__ A, const float* __restrict__ W,
          const float* __restrict__ dinv, float* __restrict__ C, int n) {
    constexpr int TX = BN / TN;         // 16 or 8
    constexpr int NT = (BM / TM) * TX;  // 256
    constexpr int KP = K + 4;
    extern __shared__ float smem[];
    float* As = smem;                   // [BM][KP]
    float* Ws = smem + BM * KP;         // [K][BN]
    const int tid = threadIdx.x;
    const int tx = tid % TX, ty = tid / TX;
    const int row0 = blockIdx.x * BM;

    for (int i = tid; i < K * BN / 4; i += NT)
        reinterpret_cast<float4*>(Ws)[i] = reinterpret_cast<const float4*>(W)[i];
    constexpr int K4 = K / 4;
    for (int i = tid; i < BM * K4; i += NT) {
        int r = i / K4, kq = i % K4;
        float4 v = {0.f, 0.f, 0.f, 0.f};
        if (row0 + r < n)
            v = reinterpret_cast<const float4*>(A + (size_t)(row0 + r) * K)[kq];
        reinterpret_cast<float4*>(As + r * KP)[kq] = v;
    }
    __syncthreads();

    float acc[TM][TN] = {};
    for (int k0 = 0; k0 < K; k0 += 4) {
        float4 wv[4];
#pragma unroll
        for (int kk = 0; kk < 4; kk++)
            wv[kk] = *reinterpret_cast<const float4*>(&Ws[(k0 + kk) * BN + tx * TN]);
#pragma unroll
        for (int i = 0; i < TM; i++) {
            float4 av = *reinterpret_cast<const float4*>(&As[(ty * TM + i) * KP + k0]);
#pragma unroll
            for (int j = 0; j < TN; j++) {
                acc[i][j] = fmaf(av.x, reinterpret_cast<const float*>(&wv[0])[j], acc[i][j]);
                acc[i][j] = fmaf(av.y, reinterpret_cast<const float*>(&wv[1])[j], acc[i][j]);
                acc[i][j] = fmaf(av.z, reinterpret_cast<const float*>(&wv[2])[j], acc[i][j]);
                acc[i][j] = fmaf(av.w, reinterpret_cast<const float*>(&wv[3])[j], acc[i][j]);
            }
        }
    }
#pragma unroll
    for (int i = 0; i < TM; i++) {
        int r = row0 + ty * TM + i;
        if (r < n) {
            float d = dinv[r];
            float4 o;
            o.x = acc[i][0] * d; o.y = acc[i][1] * d;
            o.z = acc[i][2] * d; o.w = acc[i][3] * d;
            *reinterpret_cast<float4*>(&C[(size_t)r * BN + tx * TN]) = o;
        }
    }
}

// ---------------- layer-1 aggregation (CSR gather, warp/node, float2 lanes) ----------------
__global__ void agg1_kernel(const float* __restrict__ b1) {
    int node = blockIdx.x * 8 + (threadIdx.x >> 5);
    int lane = threadIdx.x & 31;
    if (node >= NN) return;
    int beg = g_rows[node], cnt = g_cnt[node];
    const float2* __restrict__ h = reinterpret_cast<const float2*>(g_h1s);
    float2 acc = {0.f, 0.f};
    int j = 0;
    for (; j + 4 <= cnt; j += 4) {
        int s0 = g_col[beg + j], s1 = g_col[beg + j + 1];
        int s2 = g_col[beg + j + 2], s3 = g_col[beg + j + 3];
        float2 v0 = h[s0 * 32 + lane];
        float2 v1 = h[s1 * 32 + lane];
        float2 v2 = h[s2 * 32 + lane];
        float2 v3 = h[s3 * 32 + lane];
        acc.x += (v0.x + v1.x) + (v2.x + v3.x);
        acc.y += (v0.y + v1.y) + (v2.y + v3.y);
    }
    for (; j < cnt; j++) {
        int s = g_col[beg + j];
        float2 v = h[s * 32 + lane];
        acc.x += v.x; acc.y += v.y;
    }
    float di = g_dinv[node];
    float2 self = h[node * 32 + lane];
    float2 bb = reinterpret_cast<const float2*>(b1)[lane];
    float2 o;
    o.x = fmaxf(fmaf(di, acc.x + self.x, bb.x), 0.f);
    o.y = fmaxf(fmaf(di, acc.y + self.y, bb.y), 0.f);
    reinterpret_cast<float2*>(g_x1)[node * 32 + lane] = o;
}

// ---------------- layer-2 aggregation + scorer fused (warp/node, scalar lanes) ----------------
__global__ void agg2_final_kernel(const float* __restrict__ b2, const float* __restrict__ fcw,
                                  const float* __restrict__ fcb, float* __restrict__ out) {
    int node = blockIdx.x * 8 + (threadIdx.x >> 5);
    int lane = threadIdx.x & 31;
    if (node >= NN) return;
    int beg = g_rows[node], cnt = g_cnt[node];
    float acc = 0.f;
    int j = 0;
    for (; j + 4 <= cnt; j += 4) {
        int s0 = g_col[beg + j], s1 = g_col[beg + j + 1];
        int s2 = g_col[beg + j + 2], s3 = g_col[beg + j + 3];
        float v0 = g_h2s[s0 * 32 + lane];
        float v1 = g_h2s[s1 * 32 + lane];
        float v2 = g_h2s[s2 * 32 + lane];
        float v3 = g_h2s[s3 * 32 + lane];
        acc += (v0 + v1) + (v2 + v3);
    }
    for (; j < cnt; j++)
        acc += g_h2s[g_col[beg + j] * 32 + lane];
    float di = g_dinv[node];
    float v = fmaf(di, acc + g_h2s[node * 32 + lane], b2[lane]);
    v = fmaxf(v, 0.f);
    out[NN + node * 32 + lane] = v;          // h output
    float s = v * fcw[lane];
#pragma unroll
    for (int off = 16; off > 0; off >>= 1)
        s += __shfl_down_sync(0xffffffffu, s, off);
    if (lane == 0) out[node] = s + fcb[0];   // score output
}

// ---------------- launch ----------------
extern "C" void kernel_launch(void* const* d_in, const int* in_sizes, int n_in,
                              void* d_out, int out_size) {
    const float* x   = (const float*)d_in[0];
    const int*   ei  = (const int*)  d_in[1];
    const float* W1  = (const float*)d_in[2];
    const float* b1  = (const float*)d_in[3];
    const float* W2  = (const float*)d_in[4];
    const float* b2  = (const float*)d_in[5];
    const float* fcw = (const float*)d_in[6];
    const float* fcb = (const float*)d_in[7];
    float* out = (float*)d_out;

    const int* src = ei;
    const int* dst = ei + EE;

    float *h1s, *x1, *h2s, *dinv;
    cudaGetSymbolAddress((void**)&h1s,  g_h1s);
    cudaGetSymbolAddress((void**)&x1,   g_x1);
    cudaGetSymbolAddress((void**)&h2s,  g_h2s);
    cudaGetSymbolAddress((void**)&dinv, g_dinv);

    // CSR build
    zero_cnt_kernel<<<(NN + 255) / 256, 256>>>();
    hist_kernel<<<(EE + 511) / 512, 512>>>(dst);
    scan1_kernel<<<NB_SCAN, 256>>>();
    scan2_kernel<<<1, 128>>>();
    scan3_kernel<<<(NN + 255) / 256, 256>>>();
    scatter_kernel<<<(EE + 511) / 512, 512>>>(src, dst);

    // layer 1
    constexpr int SM1 = (128 * (KDIN + 4) + KDIN * DH) * 4;
    static bool attr_done = false;
    cudaFuncSetAttribute((const void*)gemm_dinv<128, DH, KDIN, 8, 4>,
                         cudaFuncAttributeMaxDynamicSharedMemorySize, SM1);
    gemm_dinv<128, DH, KDIN, 8, 4><<<(NN + 127) / 128, 256, SM1>>>(x, W1, dinv, h1s, NN);
    agg1_kernel<<<(NN + 7) / 8, 256>>>(b1);

    // layer 2
    constexpr int SM2 = (128 * (DH + 4) + DH * DOUT) * 4;
    cudaFuncSetAttribute((const void*)gemm_dinv<128, DOUT, DH, 4, 4>,
                         cudaFuncAttributeMaxDynamicSharedMemorySize, SM2);
    gemm_dinv<128, DOUT, DH, 4, 4><<<(NN + 127) / 128, 256, SM2>>>(x1, W2, dinv, h2s, NN);
    agg2_final_kernel<<<(NN + 7) / 8, 256>>>(b2, fcw, fcb, out);
    (void)attr_done; (void)in_sizes; (void)n_in; (void)out_size;
}

// round 6
// speedup vs baseline: 1.6400x; 1.0861x over previous
#include <cuda_runtime.h>
#include <cuda_fp16.h>

#define NN   100000
#define EE   1600000
#define KDIN 128
#define DH   64
#define DOUT 32
#define NB_SCAN 98          // ceil(NN/1024)

// ---------------- scratch (static device globals; no allocation) ----------------
__device__ __align__(16) int    g_cnt   [NN];        // in-degree (histogram)
__device__ __align__(16) int    g_rows  [NN];        // CSR row start
__device__ __align__(16) int    g_cursor[NN];        // scatter cursor
__device__ __align__(16) int    g_col   [EE];        // CSR column (src) indices
__device__ __align__(16) int    g_bsum  [128];
__device__ __align__(16) float  g_dinv  [NN];
__device__ __align__(16) __half g_h1s   [NN * DH];   // (x@W1) * dinv[row], fp16
__device__ __align__(16) float  g_x1    [NN * DH];   // relu'd layer-1 output (fp32)
__device__ __align__(16) __half g_h2s   [NN * DOUT]; // (x1@W2) * dinv[row], fp16

// ---------------- CSR build ----------------
__global__ void zero_cnt_kernel() {
    int i = blockIdx.x * blockDim.x + threadIdx.x;
    if (i < NN) g_cnt[i] = 0;
}

__global__ void hist_kernel(const int* __restrict__ dst) {
    int e = blockIdx.x * blockDim.x + threadIdx.x;
    if (e < EE) atomicAdd(&g_cnt[dst[e]], 1);
}

// per-block (1024 elems) exclusive scan; writes in-block exclusive prefix + block sum
__global__ void scan1_kernel() {
    __shared__ int wsum[8], woff[8];
    int tid = threadIdx.x, b = blockIdx.x;
    int lane = tid & 31, warp = tid >> 5;
    int base = b * 1024 + tid * 4;
    int v[4];
#pragma unroll
    for (int j = 0; j < 4; j++) v[j] = (base + j < NN) ? g_cnt[base + j] : 0;
    int ts = v[0] + v[1] + v[2] + v[3];
    int incl = ts;
#pragma unroll
    for (int o = 1; o < 32; o <<= 1) {
        int x = __shfl_up_sync(0xffffffffu, incl, o);
        if (lane >= o) incl += x;
    }
    int excl = incl - ts;
    if (lane == 31) wsum[warp] = incl;
    __syncthreads();
    if (tid == 0) {
        int r = 0;
#pragma unroll
        for (int w = 0; w < 8; w++) { woff[w] = r; r += wsum[w]; }
        g_bsum[b] = r;
    }
    __syncthreads();
    int off = woff[warp] + excl;
    int pre = 0;
#pragma unroll
    for (int j = 0; j < 4; j++) {
        if (base + j < NN) g_rows[base + j] = off + pre;
        pre += v[j];
    }
}

// finalize: per-block offset via warp reduce over preceding block sums (replaces scan2)
__global__ void scan3_kernel() {
    __shared__ int s_off;
    int tid = threadIdx.x;
    int chunk = (blockIdx.x * 256) >> 10;   // which 1024-chunk this block lives in
    if (tid < 32) {
        int sum = 0;
        for (int j = tid; j < chunk; j += 32) sum += g_bsum[j];
#pragma unroll
        for (int o = 16; o > 0; o >>= 1) sum += __shfl_down_sync(0xffffffffu, sum, o);
        if (tid == 0) s_off = sum;
    }
    __syncthreads();
    int i = blockIdx.x * 256 + tid;
    if (i >= NN) return;
    int rs = g_rows[i] + s_off;
    g_rows[i] = rs;
    g_cursor[i] = rs;
    g_dinv[i] = rsqrtf((float)g_cnt[i] + 1.0f);
}

__global__ void scatter_kernel(const int* __restrict__ src, const int* __restrict__ dst) {
    int e = blockIdx.x * blockDim.x + threadIdx.x;
    if (e >= EE) return;
    int d = dst[e];
    int p = atomicAdd(&g_cursor[d], 1);
    g_col[p] = src[e];
}

// ---------------- GEMM: C[r,:] = (A[r,:] @ W) * dinv[r], whole-K in smem, fp16 out ----------------
template<int BM, int BN, int K, int TM, int TN>
__global__ void __launch_bounds__(256, 2)
gemm_dinv_h(const float* __restrict__ A, const float* __restrict__ W,
            const float* __restrict__ dinv, __half* __restrict__ C, int n) {
    constexpr int TX = BN / TN;
    constexpr int NT = (BM / TM) * TX;  // 256
    constexpr int KP = K + 4;
    extern __shared__ float smem[];
    float* As = smem;                   // [BM][KP]
    float* Ws = smem + BM * KP;         // [K][BN]
    const int tid = threadIdx.x;
    const int tx = tid % TX, ty = tid / TX;
    const int row0 = blockIdx.x * BM;

    for (int i = tid; i < K * BN / 4; i += NT)
        reinterpret_cast<float4*>(Ws)[i] = reinterpret_cast<const float4*>(W)[i];
    constexpr int K4 = K / 4;
    for (int i = tid; i < BM * K4; i += NT) {
        int r = i / K4, kq = i % K4;
        float4 v = {0.f, 0.f, 0.f, 0.f};
        if (row0 + r < n)
            v = reinterpret_cast<const float4*>(A + (size_t)(row0 + r) * K)[kq];
        reinterpret_cast<float4*>(As + r * KP)[kq] = v;
    }
    __syncthreads();

    float acc[TM][TN] = {};
    for (int k0 = 0; k0 < K; k0 += 4) {
        float4 wv[4];
#pragma unroll
        for (int kk = 0; kk < 4; kk++)
            wv[kk] = *reinterpret_cast<const float4*>(&Ws[(k0 + kk) * BN + tx * TN]);
#pragma unroll
        for (int i = 0; i < TM; i++) {
            float4 av = *reinterpret_cast<const float4*>(&As[(ty * TM + i) * KP + k0]);
#pragma unroll
            for (int j = 0; j < TN; j++) {
                acc[i][j] = fmaf(av.x, reinterpret_cast<const float*>(&wv[0])[j], acc[i][j]);
                acc[i][j] = fmaf(av.y, reinterpret_cast<const float*>(&wv[1])[j], acc[i][j]);
                acc[i][j] = fmaf(av.z, reinterpret_cast<const float*>(&wv[2])[j], acc[i][j]);
                acc[i][j] = fmaf(av.w, reinterpret_cast<const float*>(&wv[3])[j], acc[i][j]);
            }
        }
    }
#pragma unroll
    for (int i = 0; i < TM; i++) {
        int r = row0 + ty * TM + i;
        if (r < n) {
            float d = dinv[r];
            __half2 p0 = __floats2half2_rn(acc[i][0] * d, acc[i][1] * d);
            __half2 p1 = __floats2half2_rn(acc[i][2] * d, acc[i][3] * d);
            uint2 u;
            u.x = *reinterpret_cast<unsigned*>(&p0);
            u.y = *reinterpret_cast<unsigned*>(&p1);
            *reinterpret_cast<uint2*>(&C[(size_t)r * BN + tx * TN]) = u;
        }
    }
}

// ---------------- layer-1 aggregation: warp/node, lane = half2 channel pair ----------------
__global__ void agg1_kernel(const float* __restrict__ b1) {
    int node = blockIdx.x * 8 + (threadIdx.x >> 5);
    int lane = threadIdx.x & 31;
    if (node >= NN) return;
    int beg = g_rows[node], cnt = g_cnt[node];
    const __half2* __restrict__ h = reinterpret_cast<const __half2*>(g_h1s);
    float2 acc = {0.f, 0.f};
    int j = 0;
    for (; j + 4 <= cnt; j += 4) {
        int s0 = g_col[beg + j], s1 = g_col[beg + j + 1];
        int s2 = g_col[beg + j + 2], s3 = g_col[beg + j + 3];
        float2 v0 = __half22float2(h[s0 * 32 + lane]);
        float2 v1 = __half22float2(h[s1 * 32 + lane]);
        float2 v2 = __half22float2(h[s2 * 32 + lane]);
        float2 v3 = __half22float2(h[s3 * 32 + lane]);
        acc.x += (v0.x + v1.x) + (v2.x + v3.x);
        acc.y += (v0.y + v1.y) + (v2.y + v3.y);
    }
    for (; j < cnt; j++) {
        float2 v = __half22float2(h[g_col[beg + j] * 32 + lane]);
        acc.x += v.x; acc.y += v.y;
    }
    float di = g_dinv[node];
    float2 self = __half22float2(h[node * 32 + lane]);
    float2 bb = reinterpret_cast<const float2*>(b1)[lane];
    float2 o;
    o.x = fmaxf(fmaf(di, acc.x + self.x, bb.x), 0.f);
    o.y = fmaxf(fmaf(di, acc.y + self.y, bb.y), 0.f);
    reinterpret_cast<float2*>(g_x1)[node * 32 + lane] = o;
}

// ---------------- layer-2 agg + scorer: 2 nodes/warp, half-warp of 16 half2 lanes ----------------
__global__ void agg2_final_kernel(const float* __restrict__ b2, const float* __restrict__ fcw,
                                  const float* __restrict__ fcb, float* __restrict__ out) {
    int warp = blockIdx.x * 8 + (threadIdx.x >> 5);
    int lane = threadIdx.x & 31;
    int half = lane >> 4;        // which node of the pair
    int hl   = lane & 15;        // channel pair index (2 channels)
    int node = warp * 2 + half;
    if (node >= NN) return;
    int beg = g_rows[node], cnt = g_cnt[node];
    const __half2* __restrict__ h = reinterpret_cast<const __half2*>(g_h2s);
    float2 acc = {0.f, 0.f};
    int j = 0;
    for (; j + 4 <= cnt; j += 4) {
        int s0 = g_col[beg + j], s1 = g_col[beg + j + 1];
        int s2 = g_col[beg + j + 2], s3 = g_col[beg + j + 3];
        float2 v0 = __half22float2(h[s0 * 16 + hl]);
        float2 v1 = __half22float2(h[s1 * 16 + hl]);
        float2 v2 = __half22float2(h[s2 * 16 + hl]);
        float2 v3 = __half22float2(h[s3 * 16 + hl]);
        acc.x += (v0.x + v1.x) + (v2.x + v3.x);
        acc.y += (v0.y + v1.y) + (v2.y + v3.y);
    }
    for (; j < cnt; j++) {
        float2 v = __half22float2(h[g_col[beg + j] * 16 + hl]);
        acc.x += v.x; acc.y += v.y;
    }
    float di = g_dinv[node];
    float2 self = __half22float2(h[node * 16 + hl]);
    float2 bb = reinterpret_cast<const float2*>(b2)[hl];
    float2 o;
    o.x = fmaxf(fmaf(di, acc.x + self.x, bb.x), 0.f);
    o.y = fmaxf(fmaf(di, acc.y + self.y, bb.y), 0.f);
    reinterpret_cast<float2*>(out + NN)[node * 16 + hl] = o;   // h output
    float2 fw = reinterpret_cast<const float2*>(fcw)[hl];
    float s = o.x * fw.x + o.y * fw.y;
#pragma unroll
    for (int off = 8; off > 0; off >>= 1)
        s += __shfl_down_sync(0xffffffffu, s, off, 16);
    if (hl == 0) out[node] = s + fcb[0];                       // score output
}

// ---------------- launch ----------------
extern "C" void kernel_launch(void* const* d_in, const int* in_sizes, int n_in,
                              void* d_out, int out_size) {
    const float* x   = (const float*)d_in[0];
    const int*   ei  = (const int*)  d_in[1];
    const float* W1  = (const float*)d_in[2];
    const float* b1  = (const float*)d_in[3];
    const float* W2  = (const float*)d_in[4];
    const float* b2  = (const float*)d_in[5];
    const float* fcw = (const float*)d_in[6];
    const float* fcb = (const float*)d_in[7];
    float* out = (float*)d_out;

    const int* src = ei;
    const int* dst = ei + EE;

    __half *h1s, *h2s;
    float *x1, *dinv;
    cudaGetSymbolAddress((void**)&h1s,  g_h1s);
    cudaGetSymbolAddress((void**)&x1,   g_x1);
    cudaGetSymbolAddress((void**)&h2s,  g_h2s);
    cudaGetSymbolAddress((void**)&dinv, g_dinv);

    // CSR build
    zero_cnt_kernel<<<(NN + 255) / 256, 256>>>();
    hist_kernel<<<(EE + 511) / 512, 512>>>(dst);
    scan1_kernel<<<NB_SCAN, 256>>>();
    scan3_kernel<<<(NN + 255) / 256, 256>>>();
    scatter_kernel<<<(EE + 511) / 512, 512>>>(src, dst);

    // layer 1
    constexpr int SM1 = (128 * (KDIN + 4) + KDIN * DH) * 4;
    cudaFuncSetAttribute((const void*)gemm_dinv_h<128, DH, KDIN, 8, 4>,
                         cudaFuncAttributeMaxDynamicSharedMemorySize, SM1);
    gemm_dinv_h<128, DH, KDIN, 8, 4><<<(NN + 127) / 128, 256, SM1>>>(x, W1, dinv, h1s, NN);
    agg1_kernel<<<(NN + 7) / 8, 256>>>(b1);

    // layer 2
    constexpr int SM2 = (128 * (DH + 4) + DH * DOUT) * 4;
    cudaFuncSetAttribute((const void*)gemm_dinv_h<128, DOUT, DH, 4, 4>,
                         cudaFuncAttributeMaxDynamicSharedMemorySize, SM2);
    gemm_dinv_h<128, DOUT, DH, 4, 4><<<(NN + 127) / 128, 256, SM2>>>(x1, W2, dinv, h2s, NN);
    agg2_final_kernel<<<(NN + 15) / 16, 256>>>(b2, fcw, fcb, out);
    (void)in_sizes; (void)n_in; (void)out_size;
}

// round 7
// speedup vs baseline: 1.8412x; 1.1227x over previous
#include <cuda_runtime.h>
#include <cuda_fp16.h>

#define NN   100000
#define EE   1600000
#define KDIN 128
#define DH   64
#define DOUT 32
#define NB_SCAN 98          // ceil(NN/1024)

// ---------------- scratch (static device globals; no allocation) ----------------
__device__ __align__(16) int    g_cnt   [NN];
__device__ __align__(16) int    g_rows  [NN];
__device__ __align__(16) int    g_cursor[NN];
__device__ __align__(16) int    g_col   [EE];
__device__ __align__(16) int    g_bsum  [128];
__device__ __align__(16) float  g_dinv  [NN];
__device__ __align__(16) __half g_h1s   [NN * DH];   // (x@W1) * dinv[row], fp16
__device__ __align__(16) float  g_x1    [NN * DH];   // relu'd layer-1 output (fp32)
__device__ __align__(16) __half g_h2s   [NN * DOUT]; // (x1@W2) * dinv[row], fp16

// ---------------- CSR build ----------------
__global__ void zero_cnt_kernel() {
    int i = blockIdx.x * blockDim.x + threadIdx.x;
    if (i < NN) g_cnt[i] = 0;
}

__global__ void hist_kernel(const int* __restrict__ dst) {
    int e = blockIdx.x * blockDim.x + threadIdx.x;
    if (e < EE) atomicAdd(&g_cnt[dst[e]], 1);
}

__global__ void scan1_kernel() {
    __shared__ int wsum[8], woff[8];
    int tid = threadIdx.x, b = blockIdx.x;
    int lane = tid & 31, warp = tid >> 5;
    int base = b * 1024 + tid * 4;
    int v[4];
#pragma unroll
    for (int j = 0; j < 4; j++) v[j] = (base + j < NN) ? g_cnt[base + j] : 0;
    int ts = v[0] + v[1] + v[2] + v[3];
    int incl = ts;
#pragma unroll
    for (int o = 1; o < 32; o <<= 1) {
        int x = __shfl_up_sync(0xffffffffu, incl, o);
        if (lane >= o) incl += x;
    }
    int excl = incl - ts;
    if (lane == 31) wsum[warp] = incl;
    __syncthreads();
    if (tid == 0) {
        int r = 0;
#pragma unroll
        for (int w = 0; w < 8; w++) { woff[w] = r; r += wsum[w]; }
        g_bsum[b] = r;
    }
    __syncthreads();
    int off = woff[warp] + excl;
    int pre = 0;
#pragma unroll
    for (int j = 0; j < 4; j++) {
        if (base + j < NN) g_rows[base + j] = off + pre;
        pre += v[j];
    }
}

__global__ void scan3_kernel() {
    __shared__ int s_off;
    int tid = threadIdx.x;
    int chunk = (blockIdx.x * 256) >> 10;
    if (tid < 32) {
        int sum = 0;
        for (int j = tid; j < chunk; j += 32) sum += g_bsum[j];
#pragma unroll
        for (int o = 16; o > 0; o >>= 1) sum += __shfl_down_sync(0xffffffffu, sum, o);
        if (tid == 0) s_off = sum;
    }
    __syncthreads();
    int i = blockIdx.x * 256 + tid;
    if (i >= NN) return;
    int rs = g_rows[i] + s_off;
    g_rows[i] = rs;
    g_cursor[i] = rs;
    g_dinv[i] = rsqrtf((float)g_cnt[i] + 1.0f);
}

__global__ void scatter_kernel(const int* __restrict__ src, const int* __restrict__ dst) {
    int e = blockIdx.x * blockDim.x + threadIdx.x;
    if (e >= EE) return;
    int d = dst[e];
    int p = atomicAdd(&g_cursor[d], 1);
    g_col[p] = src[e];
}

// ---------------- tf32x3 tensor-core GEMM ----------------
__device__ __forceinline__ float tf32_hi(float x) {
    unsigned u;
    asm("cvt.rna.tf32.f32 %0, %1;" : "=r"(u) : "f"(x));
    return __uint_as_float(u);
}

__device__ __forceinline__ void mma8(float c[4], const unsigned a[4], const unsigned b[2]) {
    asm volatile("mma.sync.aligned.m16n8k8.row.col.f32.tf32.tf32.f32 "
                 "{%0,%1,%2,%3}, {%4,%5,%6,%7}, {%8,%9}, {%0,%1,%2,%3};"
                 : "+f"(c[0]), "+f"(c[1]), "+f"(c[2]), "+f"(c[3])
                 : "r"(a[0]), "r"(a[1]), "r"(a[2]), "r"(a[3]), "r"(b[0]), "r"(b[1]));
}

// C[r,:] = (A[r,:K] @ W[K,BN]) * dinv[r]  -> fp16.  256 threads, warp = 16 rows.
template<int BN, int K>
__global__ void __launch_bounds__(256)
gemm_mma(const float* __restrict__ A, const float* __restrict__ W,
         const float* __restrict__ dinv, __half* __restrict__ C, int n) {
    constexpr int BM = 128;
    constexpr int KT = 64;              // staged k-tile
    constexpr int KP = KT + 4;          // As pitch  (4 mod 32 -> conflict-free frags)
    constexpr int WP = K + 4;           // W  pitch
    constexpr int NTILES = BN / 8;
    extern __shared__ float smem[];
    float* As = smem;                   // [BM][KP]
    float* Wh = smem + BM * KP;         // [BN][WP]  tf32-hi, transposed
    float* Wl = Wh + BN * WP;           // [BN][WP]  tf32-lo

    const int tid  = threadIdx.x;
    const int lane = tid & 31, warp = tid >> 5;
    const int g = lane >> 2, t = lane & 3;
    const int row0 = blockIdx.x * BM;
    const int wm = warp * 16;

    // stage W transposed + split (once per block)
    for (int i = tid; i < K * BN; i += 256) {
        int k = i / BN, nn = i % BN;
        float w = W[i];
        float h = tf32_hi(w);
        Wh[nn * WP + k] = h;
        Wl[nn * WP + k] = tf32_hi(w - h);
    }

    float c[NTILES][4];
#pragma unroll
    for (int nt = 0; nt < NTILES; nt++)
#pragma unroll
        for (int j = 0; j < 4; j++) c[nt][j] = 0.f;

    for (int kt = 0; kt < K; kt += KT) {
        if (kt) __syncthreads();
        constexpr int KT4 = KT / 4;
        for (int i = tid; i < BM * KT4; i += 256) {
            int r = i / KT4, kq = i % KT4;
            float4 v = {0.f, 0.f, 0.f, 0.f};
            if (row0 + r < n)
                v = *reinterpret_cast<const float4*>(A + (size_t)(row0 + r) * K + kt + kq * 4);
            *reinterpret_cast<float4*>(As + r * KP + kq * 4) = v;
        }
        __syncthreads();   // also orders W staging before first use

#pragma unroll
        for (int k0 = 0; k0 < KT; k0 += 8) {
            float a[4];
            a[0] = As[(wm + g)     * KP + k0 + t];
            a[1] = As[(wm + g + 8) * KP + k0 + t];
            a[2] = As[(wm + g)     * KP + k0 + t + 4];
            a[3] = As[(wm + g + 8) * KP + k0 + t + 4];
            unsigned ah[4], al[4];
#pragma unroll
            for (int j = 0; j < 4; j++) {
                float h = tf32_hi(a[j]);
                ah[j] = __float_as_uint(h);
                al[j] = __float_as_uint(tf32_hi(a[j] - h));
            }
            const int kg = kt + k0;
#pragma unroll
            for (int nt = 0; nt < NTILES; nt++) {
                const int wr = (nt * 8 + g) * WP + kg + t;
                unsigned bh[2], bl[2];
                bh[0] = __float_as_uint(Wh[wr]);
                bh[1] = __float_as_uint(Wh[wr + 4]);
                bl[0] = __float_as_uint(Wl[wr]);
                bl[1] = __float_as_uint(Wl[wr + 4]);
                mma8(c[nt], ah, bh);
                mma8(c[nt], ah, bl);
                mma8(c[nt], al, bh);
            }
        }
    }

    // epilogue: dinv scale + fp16 pack (c0,c1 -> row r0 cols 2t,2t+1; c2,c3 -> r0+8)
    const int r0 = row0 + wm + g, r1 = r0 + 8;
    const float d0 = (r0 < n) ? dinv[r0] : 0.f;
    const float d1 = (r1 < n) ? dinv[r1] : 0.f;
#pragma unroll
    for (int nt = 0; nt < NTILES; nt++) {
        const int colb = nt * 8 + 2 * t;
        if (r0 < n)
            *reinterpret_cast<__half2*>(&C[(size_t)r0 * BN + colb]) =
                __floats2half2_rn(c[nt][0] * d0, c[nt][1] * d0);
        if (r1 < n)
            *reinterpret_cast<__half2*>(&C[(size_t)r1 * BN + colb]) =
                __floats2half2_rn(c[nt][2] * d1, c[nt][3] * d1);
    }
}

// ---------------- layer-1 aggregation: warp/node, lane = half2 channel pair ----------------
__global__ void agg1_kernel(const float* __restrict__ b1) {
    int node = blockIdx.x * 8 + (threadIdx.x >> 5);
    int lane = threadIdx.x & 31;
    if (node >= NN) return;
    int beg = g_rows[node], cnt = g_cnt[node];
    const __half2* __restrict__ h = reinterpret_cast<const __half2*>(g_h1s);
    float2 acc = {0.f, 0.f};
    int j = 0;
    for (; j + 4 <= cnt; j += 4) {
        int s0 = g_col[beg + j], s1 = g_col[beg + j + 1];
        int s2 = g_col[beg + j + 2], s3 = g_col[beg + j + 3];
        float2 v0 = __half22float2(h[s0 * 32 + lane]);
        float2 v1 = __half22float2(h[s1 * 32 + lane]);
        float2 v2 = __half22float2(h[s2 * 32 + lane]);
        float2 v3 = __half22float2(h[s3 * 32 + lane]);
        acc.x += (v0.x + v1.x) + (v2.x + v3.x);
        acc.y += (v0.y + v1.y) + (v2.y + v3.y);
    }
    for (; j < cnt; j++) {
        float2 v = __half22float2(h[g_col[beg + j] * 32 + lane]);
        acc.x += v.x; acc.y += v.y;
    }
    float di = g_dinv[node];
    float2 self = __half22float2(h[node * 32 + lane]);
    float2 bb = reinterpret_cast<const float2*>(b1)[lane];
    float2 o;
    o.x = fmaxf(fmaf(di, acc.x + self.x, bb.x), 0.f);
    o.y = fmaxf(fmaf(di, acc.y + self.y, bb.y), 0.f);
    reinterpret_cast<float2*>(g_x1)[node * 32 + lane] = o;
}

// ---------------- layer-2 agg + scorer: 2 nodes/warp ----------------
__global__ void agg2_final_kernel(const float* __restrict__ b2, const float* __restrict__ fcw,
                                  const float* __restrict__ fcb, float* __restrict__ out) {
    int warp = blockIdx.x * 8 + (threadIdx.x >> 5);
    int lane = threadIdx.x & 31;
    int half = lane >> 4;
    int hl   = lane & 15;
    int node = warp * 2 + half;
    if (node >= NN) return;
    int beg = g_rows[node], cnt = g_cnt[node];
    const __half2* __restrict__ h = reinterpret_cast<const __half2*>(g_h2s);
    float2 acc = {0.f, 0.f};
    int j = 0;
    for (; j + 4 <= cnt; j += 4) {
        int s0 = g_col[beg + j], s1 = g_col[beg + j + 1];
        int s2 = g_col[beg + j + 2], s3 = g_col[beg + j + 3];
        float2 v0 = __half22float2(h[s0 * 16 + hl]);
        float2 v1 = __half22float2(h[s1 * 16 + hl]);
        float2 v2 = __half22float2(h[s2 * 16 + hl]);
        float2 v3 = __half22float2(h[s3 * 16 + hl]);
        acc.x += (v0.x + v1.x) + (v2.x + v3.x);
        acc.y += (v0.y + v1.y) + (v2.y + v3.y);
    }
    for (; j < cnt; j++) {
        float2 v = __half22float2(h[g_col[beg + j] * 16 + hl]);
        acc.x += v.x; acc.y += v.y;
    }
    float di = g_dinv[node];
    float2 self = __half22float2(h[node * 16 + hl]);
    float2 bb = reinterpret_cast<const float2*>(b2)[hl];
    float2 o;
    o.x = fmaxf(fmaf(di, acc.x + self.x, bb.x), 0.f);
    o.y = fmaxf(fmaf(di, acc.y + self.y, bb.y), 0.f);
    reinterpret_cast<float2*>(out + NN)[node * 16 + hl] = o;
    float2 fw = reinterpret_cast<const float2*>(fcw)[hl];
    float s = o.x * fw.x + o.y * fw.y;
#pragma unroll
    for (int off = 8; off > 0; off >>= 1)
        s += __shfl_down_sync(0xffffffffu, s, off, 16);
    if (hl == 0) out[node] = s + fcb[0];
}

// ---------------- launch ----------------
extern "C" void kernel_launch(void* const* d_in, const int* in_sizes, int n_in,
                              void* d_out, int out_size) {
    const float* x   = (const float*)d_in[0];
    const int*   ei  = (const int*)  d_in[1];
    const float* W1  = (const float*)d_in[2];
    const float* b1  = (const float*)d_in[3];
    const float* W2  = (const float*)d_in[4];
    const float* b2  = (const float*)d_in[5];
    const float* fcw = (const float*)d_in[6];
    const float* fcb = (const float*)d_in[7];
    float* out = (float*)d_out;

    const int* src = ei;
    const int* dst = ei + EE;

    __half *h1s, *h2s;
    float *x1, *dinv;
    cudaGetSymbolAddress((void**)&h1s,  g_h1s);
    cudaGetSymbolAddress((void**)&x1,   g_x1);
    cudaGetSymbolAddress((void**)&h2s,  g_h2s);
    cudaGetSymbolAddress((void**)&dinv, g_dinv);

    // CSR build
    zero_cnt_kernel<<<(NN + 255) / 256, 256>>>();
    hist_kernel<<<(EE + 511) / 512, 512>>>(dst);
    scan1_kernel<<<NB_SCAN, 256>>>();
    scan3_kernel<<<(NN + 255) / 256, 256>>>();
    scatter_kernel<<<(EE + 511) / 512, 512>>>(src, dst);

    // layer 1: GEMM (tf32x3 tensor cores) + gather-aggregate
    constexpr int SM1 = (128 * 68 + 2 * DH * (KDIN + 4)) * 4;     // 102400 B
    cudaFuncSetAttribute((const void*)gemm_mma<DH, KDIN>,
                         cudaFuncAttributeMaxDynamicSharedMemorySize, SM1);
    gemm_mma<DH, KDIN><<<(NN + 127) / 128, 256, SM1>>>(x, W1, dinv, h1s, NN);
    agg1_kernel<<<(NN + 7) / 8, 256>>>(b1);

    // layer 2
    constexpr int SM2 = (128 * 68 + 2 * DOUT * (DH + 4)) * 4;     // 52224 B
    cudaFuncSetAttribute((const void*)gemm_mma<DOUT, DH>,
                         cudaFuncAttributeMaxDynamicSharedMemorySize, SM2);
    gemm_mma<DOUT, DH><<<(NN + 127) / 128, 256, SM2>>>(x1, W2, dinv, h2s, NN);
    agg2_final_kernel<<<(NN + 15) / 16, 256>>>(b2, fcw, fcb, out);
    (void)in_sizes; (void)n_in; (void)out_size;
}

// round 8
// speedup vs baseline: 1.9464x; 1.0571x over previous
#include <cuda_runtime.h>
#include <cuda_fp16.h>

#define NN   100000
#define EE   1600000
#define KDIN 128
#define DH   64
#define DOUT 32
#define NB_SCAN 98          // ceil(NN/1024)

// ---------------- scratch (static device globals; zero-initialized at load) ----------------
__device__ __align__(16) int    g_cnt   [NN];        // in-degree; re-zeroed by agg2_final
__device__ __align__(16) int    g_rows  [NN];
__device__ __align__(16) int    g_cursor[NN];
__device__ __align__(16) int    g_col   [EE];
__device__ __align__(16) int    g_bsum  [128];
__device__ __align__(16) float  g_dinv  [NN];
__device__ __align__(16) __half g_h1s   [NN * DH];   // (x@W1) * dinv[row], fp16
__device__ __align__(16) __half g_x1h   [NN * DH];   // relu'd layer-1 output, fp16
__device__ __align__(16) __half g_h2s   [NN * DOUT]; // (x1@W2) * dinv[row], fp16

// ---------------- CSR build ----------------
__global__ void hist_kernel(const int* __restrict__ dst) {
    int e = blockIdx.x * blockDim.x + threadIdx.x;
    if (e < EE) atomicAdd(&g_cnt[dst[e]], 1);
}

__global__ void dinv_kernel() {
    int i = blockIdx.x * blockDim.x + threadIdx.x;
    if (i < NN) g_dinv[i] = rsqrtf((float)g_cnt[i] + 1.0f);
}

__global__ void scan1_kernel() {
    __shared__ int wsum[8], woff[8];
    int tid = threadIdx.x, b = blockIdx.x;
    int lane = tid & 31, warp = tid >> 5;
    int base = b * 1024 + tid * 4;
    int v[4];
#pragma unroll
    for (int j = 0; j < 4; j++) v[j] = (base + j < NN) ? g_cnt[base + j] : 0;
    int ts = v[0] + v[1] + v[2] + v[3];
    int incl = ts;
#pragma unroll
    for (int o = 1; o < 32; o <<= 1) {
        int x = __shfl_up_sync(0xffffffffu, incl, o);
        if (lane >= o) incl += x;
    }
    int excl = incl - ts;
    if (lane == 31) wsum[warp] = incl;
    __syncthreads();
    if (tid == 0) {
        int r = 0;
#pragma unroll
        for (int w = 0; w < 8; w++) { woff[w] = r; r += wsum[w]; }
        g_bsum[b] = r;
    }
    __syncthreads();
    int off = woff[warp] + excl;
    int pre = 0;
#pragma unroll
    for (int j = 0; j < 4; j++) {
        if (base + j < NN) g_rows[base + j] = off + pre;
        pre += v[j];
    }
}

__global__ void scan3_kernel() {
    __shared__ int s_off;
    int tid = threadIdx.x;
    int chunk = (blockIdx.x * 256) >> 10;
    if (tid < 32) {
        int sum = 0;
        for (int j = tid; j < chunk; j += 32) sum += g_bsum[j];
#pragma unroll
        for (int o = 16; o > 0; o >>= 1) sum += __shfl_down_sync(0xffffffffu, sum, o);
        if (tid == 0) s_off = sum;
    }
    __syncthreads();
    int i = blockIdx.x * 256 + tid;
    if (i >= NN) return;
    int rs = g_rows[i] + s_off;
    g_rows[i] = rs;
    g_cursor[i] = rs;
}

__global__ void scatter_kernel(const int* __restrict__ src, const int* __restrict__ dst) {
    int e = blockIdx.x * blockDim.x + threadIdx.x;
    if (e >= EE) return;
    int d = dst[e];
    int p = atomicAdd(&g_cursor[d], 1);
    g_col[p] = src[e];
}

// ---------------- tf32x3 tensor-core GEMM ----------------
__device__ __forceinline__ float tf32_hi(float x) {
    unsigned u;
    asm("cvt.rna.tf32.f32 %0, %1;" : "=r"(u) : "f"(x));
    return __uint_as_float(u);
}

__device__ __forceinline__ void mma8(float c[4], const unsigned a[4], const unsigned b[2]) {
    asm volatile("mma.sync.aligned.m16n8k8.row.col.f32.tf32.tf32.f32 "
                 "{%0,%1,%2,%3}, {%4,%5,%6,%7}, {%8,%9}, {%0,%1,%2,%3};"
                 : "+f"(c[0]), "+f"(c[1]), "+f"(c[2]), "+f"(c[3])
                 : "r"(a[0]), "r"(a[1]), "r"(a[2]), "r"(a[3]), "r"(b[0]), "r"(b[1]));
}

// C[r,:] = (A[r,:K] @ W[K,BN]) * dinv[r] -> fp16.  256 threads, warp = 16 rows.
// HALF_IN: A is fp16 (converted on stage-in), else fp32.
template<int BN, int K, bool HALF_IN>
__global__ void __launch_bounds__(256)
gemm_mma(const void* __restrict__ Av, const float* __restrict__ W,
         const float* __restrict__ dinv, __half* __restrict__ C, int n) {
    constexpr int BM = 128;
    constexpr int KT = 64;
    constexpr int KP = KT + 4;
    constexpr int WP = K + 4;
    constexpr int NTILES = BN / 8;
    extern __shared__ float smem[];
    float* As = smem;                   // [BM][KP]
    float* Wh = smem + BM * KP;         // [BN][WP]
    float* Wl = Wh + BN * WP;

    const int tid  = threadIdx.x;
    const int lane = tid & 31, warp = tid >> 5;
    const int g = lane >> 2, t = lane & 3;
    const int row0 = blockIdx.x * BM;
    const int wm = warp * 16;

    for (int i = tid; i < K * BN; i += 256) {
        int k = i / BN, nn = i % BN;
        float w = W[i];
        float h = tf32_hi(w);
        Wh[nn * WP + k] = h;
        Wl[nn * WP + k] = tf32_hi(w - h);
    }

    float c[NTILES][4];
#pragma unroll
    for (int nt = 0; nt < NTILES; nt++)
#pragma unroll
        for (int j = 0; j < 4; j++) c[nt][j] = 0.f;

    for (int kt = 0; kt < K; kt += KT) {
        if (kt) __syncthreads();
        constexpr int KT4 = KT / 4;
        for (int i = tid; i < BM * KT4; i += 256) {
            int r = i / KT4, kq = i % KT4;
            float4 v = {0.f, 0.f, 0.f, 0.f};
            if (row0 + r < n) {
                if (HALF_IN) {
                    const __half* A = (const __half*)Av;
                    uint2 u = *reinterpret_cast<const uint2*>(A + (size_t)(row0 + r) * K + kt + kq * 4);
                    float2 f0 = __half22float2(*reinterpret_cast<__half2*>(&u.x));
                    float2 f1 = __half22float2(*reinterpret_cast<__half2*>(&u.y));
                    v.x = f0.x; v.y = f0.y; v.z = f1.x; v.w = f1.y;
                } else {
                    const float* A = (const float*)Av;
                    v = *reinterpret_cast<const float4*>(A + (size_t)(row0 + r) * K + kt + kq * 4);
                }
            }
            *reinterpret_cast<float4*>(As + r * KP + kq * 4) = v;
        }
        __syncthreads();

#pragma unroll
        for (int k0 = 0; k0 < KT; k0 += 8) {
            float a[4];
            a[0] = As[(wm + g)     * KP + k0 + t];
            a[1] = As[(wm + g + 8) * KP + k0 + t];
            a[2] = As[(wm + g)     * KP + k0 + t + 4];
            a[3] = As[(wm + g + 8) * KP + k0 + t + 4];
            unsigned ah[4], al[4];
#pragma unroll
            for (int j = 0; j < 4; j++) {
                float h = tf32_hi(a[j]);
                ah[j] = __float_as_uint(h);
                al[j] = __float_as_uint(tf32_hi(a[j] - h));
            }
            const int kg = kt + k0;
#pragma unroll
            for (int nt = 0; nt < NTILES; nt++) {
                const int wr = (nt * 8 + g) * WP + kg + t;
                unsigned bh[2], bl[2];
                bh[0] = __float_as_uint(Wh[wr]);
                bh[1] = __float_as_uint(Wh[wr + 4]);
                bl[0] = __float_as_uint(Wl[wr]);
                bl[1] = __float_as_uint(Wl[wr + 4]);
                mma8(c[nt], ah, bh);
                mma8(c[nt], ah, bl);
                mma8(c[nt], al, bh);
            }
        }
    }

    const int r0 = row0 + wm + g, r1 = r0 + 8;
    const float d0 = (r0 < n) ? dinv[r0] : 0.f;
    const float d1 = (r1 < n) ? dinv[r1] : 0.f;
#pragma unroll
    for (int nt = 0; nt < NTILES; nt++) {
        const int colb = nt * 8 + 2 * t;
        if (r0 < n)
            *reinterpret_cast<__half2*>(&C[(size_t)r0 * BN + colb]) =
                __floats2half2_rn(c[nt][0] * d0, c[nt][1] * d0);
        if (r1 < n)
            *reinterpret_cast<__half2*>(&C[(size_t)r1 * BN + colb]) =
                __floats2half2_rn(c[nt][2] * d1, c[nt][3] * d1);
    }
}

// ---------------- layer-1 aggregation: warp/node, lane = half2 channel pair ----------------
__global__ void agg1_kernel(const float* __restrict__ b1) {
    int node = blockIdx.x * 8 + (threadIdx.x >> 5);
    int lane = threadIdx.x & 31;
    if (node >= NN) return;
    int beg = g_rows[node], cnt = g_cnt[node];
    const __half2* __restrict__ h = reinterpret_cast<const __half2*>(g_h1s);
    float2 acc = {0.f, 0.f};
    int j = 0;
    for (; j + 4 <= cnt; j += 4) {
        int s0 = g_col[beg + j], s1 = g_col[beg + j + 1];
        int s2 = g_col[beg + j + 2], s3 = g_col[beg + j + 3];
        float2 v0 = __half22float2(h[s0 * 32 + lane]);
        float2 v1 = __half22float2(h[s1 * 32 + lane]);
        float2 v2 = __half22float2(h[s2 * 32 + lane]);
        float2 v3 = __half22float2(h[s3 * 32 + lane]);
        acc.x += (v0.x + v1.x) + (v2.x + v3.x);
        acc.y += (v0.y + v1.y) + (v2.y + v3.y);
    }
    for (; j < cnt; j++) {
        float2 v = __half22float2(h[g_col[beg + j] * 32 + lane]);
        acc.x += v.x; acc.y += v.y;
    }
    float di = g_dinv[node];
    float2 self = __half22float2(h[node * 32 + lane]);
    float2 bb = reinterpret_cast<const float2*>(b1)[lane];
    float ox = fmaxf(fmaf(di, acc.x + self.x, bb.x), 0.f);
    float oy = fmaxf(fmaf(di, acc.y + self.y, bb.y), 0.f);
    reinterpret_cast<__half2*>(g_x1h)[node * 32 + lane] = __floats2half2_rn(ox, oy);
}

// ---------------- layer-2 agg + scorer: 2 nodes/warp; re-zeroes g_cnt for next replay ----------------
__global__ void agg2_final_kernel(const float* __restrict__ b2, const float* __restrict__ fcw,
                                  const float* __restrict__ fcb, float* __restrict__ out) {
    int warp = blockIdx.x * 8 + (threadIdx.x >> 5);
    int lane = threadIdx.x & 31;
    int half = lane >> 4;
    int hl   = lane & 15;
    int node = warp * 2 + half;
    if (node >= NN) return;
    int beg = g_rows[node], cnt = g_cnt[node];
    const __half2* __restrict__ h = reinterpret_cast<const __half2*>(g_h2s);
    float2 acc = {0.f, 0.f};
    int j = 0;
    for (; j + 4 <= cnt; j += 4) {
        int s0 = g_col[beg + j], s1 = g_col[beg + j + 1];
        int s2 = g_col[beg + j + 2], s3 = g_col[beg + j + 3];
        float2 v0 = __half22float2(h[s0 * 16 + hl]);
        float2 v1 = __half22float2(h[s1 * 16 + hl]);
        float2 v2 = __half22float2(h[s2 * 16 + hl]);
        float2 v3 = __half22float2(h[s3 * 16 + hl]);
        acc.x += (v0.x + v1.x) + (v2.x + v3.x);
        acc.y += (v0.y + v1.y) + (v2.y + v3.y);
    }
    for (; j < cnt; j++) {
        float2 v = __half22float2(h[g_col[beg + j] * 16 + hl]);
        acc.x += v.x; acc.y += v.y;
    }
    float di = g_dinv[node];
    float2 self = __half22float2(h[node * 16 + hl]);
    float2 bb = reinterpret_cast<const float2*>(b2)[hl];
    float2 o;
    o.x = fmaxf(fmaf(di, acc.x + self.x, bb.x), 0.f);
    o.y = fmaxf(fmaf(di, acc.y + self.y, bb.y), 0.f);
    reinterpret_cast<float2*>(out + NN)[node * 16 + hl] = o;
    float2 fw = reinterpret_cast<const float2*>(fcw)[hl];
    float s = o.x * fw.x + o.y * fw.y;
#pragma unroll
    for (int off = 8; off > 0; off >>= 1)
        s += __shfl_down_sync(0xffffffffu, s, off, 16);
    if (hl == 0) {
        out[node] = s + fcb[0];
        g_cnt[node] = 0;            // restore invariant for next graph replay
    }
}

// ---------------- launch ----------------
extern "C" void kernel_launch(void* const* d_in, const int* in_sizes, int n_in,
                              void* d_out, int out_size) {
    const float* x   = (const float*)d_in[0];
    const int*   ei  = (const int*)  d_in[1];
    const float* W1  = (const float*)d_in[2];
    const float* b1  = (const float*)d_in[3];
    const float* W2  = (const float*)d_in[4];
    const float* b2  = (const float*)d_in[5];
    const float* fcw = (const float*)d_in[6];
    const float* fcb = (const float*)d_in[7];
    float* out = (float*)d_out;

    const int* src = ei;
    const int* dst = ei + EE;

    __half *h1s, *h2s, *x1h;
    float *dinv;
    cudaGetSymbolAddress((void**)&h1s,  g_h1s);
    cudaGetSymbolAddress((void**)&x1h,  g_x1h);
    cudaGetSymbolAddress((void**)&h2s,  g_h2s);
    cudaGetSymbolAddress((void**)&dinv, g_dinv);

    // side stream + fork/join events (created once, first call is outside capture)
    static cudaStream_t s2 = [] { cudaStream_t s; cudaStreamCreateWithFlags(&s, cudaStreamNonBlocking); return s; }();
    static cudaEvent_t evH = [] { cudaEvent_t e; cudaEventCreateWithFlags(&e, cudaEventDisableTiming); return e; }();
    static cudaEvent_t evC = [] { cudaEvent_t e; cudaEventCreateWithFlags(&e, cudaEventDisableTiming); return e; }();

    // ---- main stream: hist -> dinv -> GEMM1 ----
    hist_kernel<<<(EE + 511) / 512, 512>>>(dst);
    cudaEventRecord(evH, 0);
    dinv_kernel<<<(NN + 255) / 256, 256>>>();

    constexpr int SM1 = (128 * 68 + 2 * DH * (KDIN + 4)) * 4;
    cudaFuncSetAttribute((const void*)gemm_mma<DH, KDIN, false>,
                         cudaFuncAttributeMaxDynamicSharedMemorySize, SM1);
    gemm_mma<DH, KDIN, false><<<(NN + 127) / 128, 256, SM1>>>(x, W1, dinv, h1s, NN);

    // ---- side stream (forked after hist): scan1 -> scan3 -> scatter ----
    cudaStreamWaitEvent(s2, evH, 0);
    scan1_kernel<<<NB_SCAN, 256, 0, s2>>>();
    scan3_kernel<<<(NN + 255) / 256, 256, 0, s2>>>();
    scatter_kernel<<<(EE + 511) / 512, 512, 0, s2>>>(src, dst);
    cudaEventRecord(evC, s2);

    // ---- join, then agg1 -> GEMM2 -> agg2 ----
    cudaStreamWaitEvent(0, evC, 0);
    agg1_kernel<<<(NN + 7) / 8, 256>>>(b1);

    constexpr int SM2 = (128 * 68 + 2 * DOUT * (DH + 4)) * 4;
    cudaFuncSetAttribute((const void*)gemm_mma<DOUT, DH, true>,
                         cudaFuncAttributeMaxDynamicSharedMemorySize, SM2);
    gemm_mma<DOUT, DH, true><<<(NN + 127) / 128, 256, SM2>>>(x1h, W2, dinv, h2s, NN);
    agg2_final_kernel<<<(NN + 15) / 16, 256>>>(b2, fcw, fcb, out);
    (void)in_sizes; (void)n_in; (void)out_size;
}